// round 16
// baseline (speedup 1.0000x reference)
#include <cuda_runtime.h>
#include <cuda_fp16.h>
#include <math.h>
#include <stdint.h>

#define Bdim 8
#define Cdim 32
#define Hdim 128
#define Wdim 128
#define OUTdim 32
#define HW (Hdim*Wdim)            /* 16384 */
#define NPIX (Bdim*HW)            /* 131072 */
#define NBLK_CONV 512

// ---- scratch (static device globals; no runtime allocation) ----
__device__ float g_conv[4*NPIX];          // conv+bias outputs: v0,v1,z0,z1 planes
__device__ float g_partial[NBLK_CONV*8];  // per-block partial sums (4 sums + 4 sumsq)
__device__ float g_stats[12];             // mean[4], scale[4], shift[4]
__device__ __align__(16) __half g_bh[32*512];  // w_pk fp16 plane

// =====================================================================
// Kernel A (fused): 7-tap convs + bias + BN block partials + w_pk->fp16
// =====================================================================
__global__ __launch_bounds__(256) void convbn_kernel(
    const float* __restrict__ x,
    const float* __restrict__ w_vrt, const float* __restrict__ b_vrt,
    const float* __restrict__ w_hrz, const float* __restrict__ b_hrz,
    const float* __restrict__ w_pk)
{
    __shared__ float swv[448], swh[448];
    __shared__ float part[4][256];       // [plane][rowsel*128 + w]
    __shared__ float red[4][8];
    int tid = threadIdx.x;
    for (int i = tid; i < 448; i += 256) { swv[i] = w_vrt[i]; swh[i] = w_hrz[i]; }
    // fused wsplit: each block converts its 32-element slice of w_pk
    if (tid < 32) {
        int i = blockIdx.x*32 + tid;
        g_bh[i] = __float2half_rn(w_pk[i]);
    }
    __syncthreads();

    int b      = blockIdx.x >> 6;
    int rg     = blockIdx.x & 63;
    int rowsel = (tid >> 6) & 1;
    int half   = tid >> 7;
    int row    = rg*2 + rowsel;
    int w0     = (tid & 63) * 2;
    const float* Xb = x + (size_t)b*Cdim*HW;

    float v0[2]={0,0}, v1[2]={0,0}, z0[2]={0,0}, z1[2]={0,0};

    #pragma unroll 1
    for (int cl = 0; cl < 16; ++cl) {
        int c = half*16 + cl;
        const float* Xc  = Xb + c*HW;
        const float* rp  = Xc + row*Wdim;
        #pragma unroll
        for (int t = 0; t < 7; ++t) {
            int hh = row + t - 3;
            float2 xv = (hh >= 0 && hh < Hdim) ? *(const float2*)(Xc + hh*Wdim + w0)
                                               : make_float2(0.f, 0.f);
            float wa = swv[c*7+t], wb = swv[224 + c*7+t];
            v0[0]=fmaf(xv.x,wa,v0[0]); v0[1]=fmaf(xv.y,wa,v0[1]);
            v1[0]=fmaf(xv.x,wb,v1[0]); v1[1]=fmaf(xv.y,wb,v1[1]);
        }
        float xr[10];
        #pragma unroll
        for (int l = 0; l < 5; ++l) {
            int i0 = w0 - 4 + l*2;
            float2 v = (i0 >= 0 && i0 < 127) ? *(const float2*)(rp + i0)
                                             : make_float2(0.f, 0.f);
            xr[l*2] = v.x; xr[l*2+1] = v.y;
        }
        #pragma unroll
        for (int t = 0; t < 7; ++t) {
            float wa = swh[c*7+t], wb = swh[224 + c*7+t];
            z0[0]=fmaf(xr[t+1],wa,z0[0]); z0[1]=fmaf(xr[t+2],wa,z0[1]);
            z1[0]=fmaf(xr[t+1],wb,z1[0]); z1[1]=fmaf(xr[t+2],wb,z1[1]);
        }
    }

    int sp = rowsel*128 + w0;
    if (half == 1) {
        *(float2*)&part[0][sp] = make_float2(v0[0], v0[1]);
        *(float2*)&part[1][sp] = make_float2(v1[0], v1[1]);
        *(float2*)&part[2][sp] = make_float2(z0[0], z0[1]);
        *(float2*)&part[3][sp] = make_float2(z1[0], z1[1]);
    }
    __syncthreads();

    if (half == 0) {
        float2 o0 = *(float2*)&part[0][sp];
        float2 o1 = *(float2*)&part[1][sp];
        float2 o2 = *(float2*)&part[2][sp];
        float2 o3 = *(float2*)&part[3][sp];
        float bv0 = b_vrt[0], bv1 = b_vrt[1], bh0 = b_hrz[0], bh1 = b_hrz[1];
        v0[0] += o0.x + bv0; v0[1] += o0.y + bv0;
        v1[0] += o1.x + bv1; v1[1] += o1.y + bv1;
        z0[0] += o2.x + bh0; z0[1] += o2.y + bh0;
        z1[0] += o3.x + bh1; z1[1] += o3.y + bh1;

        int pixbase = b*HW + row*Wdim + w0;
        *(float2*)&g_conv[          pixbase] = make_float2(v0[0],v0[1]);
        *(float2*)&g_conv[  NPIX +  pixbase] = make_float2(v1[0],v1[1]);
        *(float2*)&g_conv[2*NPIX +  pixbase] = make_float2(z0[0],z0[1]);
        *(float2*)&g_conv[3*NPIX +  pixbase] = make_float2(z1[0],z1[1]);

        float vals[8];
        vals[0]=v0[0]+v0[1]; vals[1]=v1[0]+v1[1]; vals[2]=z0[0]+z0[1]; vals[3]=z1[0]+z1[1];
        vals[4]=v0[0]*v0[0]+v0[1]*v0[1]; vals[5]=v1[0]*v1[0]+v1[1]*v1[1];
        vals[6]=z0[0]*z0[0]+z0[1]*z0[1]; vals[7]=z1[0]*z1[0]+z1[1]*z1[1];

        #pragma unroll
        for (int k = 0; k < 8; ++k) {
            float s = vals[k];
            #pragma unroll
            for (int off = 16; off; off >>= 1) s += __shfl_down_sync(0xffffffffu, s, off);
            if ((tid & 31) == 0) red[tid>>5][k] = s;
        }
    }
    __syncthreads();
    if (tid < 8) {
        float s = red[0][tid] + red[1][tid] + red[2][tid] + red[3][tid];
        g_partial[blockIdx.x*8 + tid] = s;
    }
}

// =====================================================================
// Kernel B: finalize BN stats — parallel reduction
// =====================================================================
__global__ __launch_bounds__(256) void stats_kernel(
    const float* __restrict__ g_vrt, const float* __restrict__ be_vrt,
    const float* __restrict__ g_hrz, const float* __restrict__ be_hrz)
{
    __shared__ float red[32][8];
    __shared__ float sh[8];
    int t = threadIdx.x;
    int k = t & 7, grp = t >> 3;

    float s = 0.f;
    #pragma unroll
    for (int j = 0; j < 16; ++j)
        s += g_partial[(grp + 32*j)*8 + k];
    red[grp][k] = s;
    __syncthreads();

    if (t < 8) {
        float acc = 0.f;
        #pragma unroll
        for (int g = 0; g < 32; ++g) acc += red[g][t];
        sh[t] = acc;
    }
    __syncthreads();

    if (t < 4) {
        const float inv = 1.f / (float)NPIX;
        float mean = sh[t] * inv;
        float var  = sh[t+4] * inv - mean*mean;
        float gamma = (t < 2) ? g_vrt[t] : g_hrz[t-2];
        float beta  = (t < 2) ? be_vrt[t] : be_hrz[t-2];
        g_stats[t]     = mean;
        g_stats[4 + t] = gamma * rsqrtf(var + 1e-5f);
        g_stats[8 + t] = beta;
    }
}

// =====================================================================
// Kernel C: fp16 1-GEMM, symmetric ping-pong, 4 CTAs/SM target.
// =====================================================================
#define BSTRIDE 520    /* halfs per B row -> 1040 B */
#define APLANE  10240  /* 128 rows x 80 B */

#define SM_BIAS 0
#define SM_B    128
#define SM_A    (SM_B + 32*BSTRIDE*2)           /* 33408; A0, A1 (parities) */
#define SM_TOTAL (SM_A + 2*APLANE)              /* 53888 */

__device__ __forceinline__ uint32_t smem_u32(const void* p) {
    uint32_t a;
    asm("{ .reg .u64 t; cvta.to.shared.u64 t, %1; cvt.u32.u64 %0, t; }" : "=r"(a) : "l"(p));
    return a;
}
__device__ __forceinline__ void mma_f16(float* c, const uint32_t* a, const uint32_t* b) {
    asm volatile(
        "mma.sync.aligned.m16n8k16.row.col.f32.f16.f16.f32 "
        "{%0,%1,%2,%3}, {%4,%5,%6,%7}, {%8,%9}, {%0,%1,%2,%3};"
        : "+f"(c[0]), "+f"(c[1]), "+f"(c[2]), "+f"(c[3])
        : "r"(a[0]), "r"(a[1]), "r"(a[2]), "r"(a[3]), "r"(b[0]), "r"(b[1]));
}
__device__ __forceinline__ void ldmx4(uint32_t* r, uint32_t addr) {
    asm volatile("ldmatrix.sync.aligned.m8n8.x4.shared.b16 {%0,%1,%2,%3}, [%4];"
        : "=r"(r[0]), "=r"(r[1]), "=r"(r[2]), "=r"(r[3]) : "r"(addr));
}
__device__ __forceinline__ void ldmx2(uint32_t* r, uint32_t addr) {
    asm volatile("ldmatrix.sync.aligned.m8n8.x2.shared.b16 {%0,%1}, [%2];"
        : "=r"(r[0]), "=r"(r[1]) : "r"(addr));
}

// raw gather of one channel: xc, 16 ring samples, 2 predicated edge samples
__device__ __forceinline__ void ldch(const float* __restrict__ Xc, int ctr,
                                     const unsigned* offp, int eBoff, int eLoff,
                                     float eBw, float eLw, float* r) {
    r[0] = __ldg(Xc + ctr);
    #pragma unroll
    for (int j = 0; j < 8; ++j) {
        r[1+2*j] = __ldg(Xc + (int)(offp[j] & 0xFFFFu));
        r[2+2*j] = __ldg(Xc + (int)(offp[j] >> 16));
    }
    r[17] = (eBw != 0.f) ? __ldg(Xc + eBoff) : 0.f;
    r[18] = (eLw != 0.f) ? __ldg(Xc + eLoff) : 0.f;
}

// convert one channel's 16 taps (single fp16), store into A plane [par]
__device__ __forceinline__ void cvtstore(char* smem, const float* r, const float* a,
                                         float eBw, float eLw, int p, int chp, int par) {
    float d[16];
    #pragma unroll
    for (int n = 0; n < 16; ++n)
        d[n] = fmaf(-a[n>>2], r[1+n], r[0]);
    d[11] = fmaf(-eBw, r[17], d[11]);
    d[15] = fmaf(-eLw, r[18], d[15]);

    uint32_t oh[8];
    #pragma unroll
    for (int j = 0; j < 8; ++j) {
        __half2 hv = __float22half2_rn(make_float2(d[2*j], d[2*j+1]));
        oh[j] = *(uint32_t*)&hv;
    }
    char* baseH = smem + SM_A + par*APLANE + p*80 + chp*32;
    ((uint4*)baseH)[0] = make_uint4(oh[0], oh[1], oh[2], oh[3]);
    ((uint4*)baseH)[1] = make_uint4(oh[4], oh[5], oh[6], oh[7]);
}

__global__ __launch_bounds__(256, 4) void main_kernel(
    const float* __restrict__ x, const float* __restrict__ b_pk,
    float* __restrict__ out)
{
    extern __shared__ char smem[];
    float* sbias = (float*)(smem + SM_BIAS);
    int tid = threadIdx.x;
    int wid = tid >> 5, lid = tid & 31;

    // --- copy fp16 B plane into padded smem rows ---
    {
        if (tid < 32) sbias[tid] = b_pk[tid];
        const uint4* sbh = (const uint4*)g_bh;
        #pragma unroll
        for (int j = 0; j < 8; ++j) {
            int u = tid + j*256;
            int o = u >> 6, q = u & 63;
            *(uint4*)(smem + SM_B + o*(BSTRIDE*2) + q*16) = sbh[u];
        }
    }

    int b   = blockIdx.x >> 7;
    int row = blockIdx.x & 127;
    int p   = tid & 127;
    int chp = tid >> 7;              // channel-in-chunk selector (0/1)
    int h = row, w = p;
    int pix = b*HW + row*Wdim + w;

    // gb0..gb3 = 2*sigmoid(BN(conv))
    float gb[4];
    #pragma unroll
    for (int j = 0; j < 4; ++j) {
        float cv = g_conv[j*NPIX + pix];
        float t = (cv - g_stats[j]) * g_stats[4+j] + g_stats[8+j];
        gb[j] = 2.f / (1.f + expf(-t));
    }

    int rm[5], cm[5];
    #pragma unroll
    for (int i = 0; i < 5; ++i) {
        rm[i] = min(max(h + i - 2, 0), 127);
        cm[i] = min(max(w + i - 2, 0), 127);
    }

    unsigned int offp[8];
    float a[4];
    float eBw, eLw; int eBoff, eLoff;
    {
        int off[16];
        float u, q, qlc, qrc, uc;
        u = (float)h - gb[0];
        q = floorf(u);
        qlc = fminf(fmaxf(q, 0.f), 131.f);
        uc  = fminf(fmaxf(u, 0.f), 131.f);
        a[0] = 1.f + qlc - uc;
        int rT = min(max((int)qlc - 2, 0), 127);
        off[0]=rT*Wdim+cm[0]; off[1]=rT*Wdim+cm[1]; off[2]=rT*Wdim+cm[2]; off[3]=rT*Wdim+cm[3];
        u = (float)w + 4.f + gb[3];
        q = floorf(u);
        qlc = fminf(fmaxf(q, 0.f), 131.f);
        uc  = fminf(fmaxf(u, 0.f), 131.f);
        a[1] = 1.f + qlc - uc;
        int cR = min(max((int)qlc - 2, 0), 127);
        off[4]=rm[0]*Wdim+cR; off[5]=rm[1]*Wdim+cR; off[6]=rm[2]*Wdim+cR; off[7]=rm[3]*Wdim+cR;
        u = (float)h + 4.f + gb[1];
        q = floorf(u);
        qlc = fminf(fmaxf(q, 0.f), 131.f);
        qrc = fminf(fmaxf(q + 1.f, 0.f), 131.f);
        uc  = fminf(fmaxf(u, 0.f), 131.f);
        a[2] = 1.f + qlc - uc;
        float aBr = 1.f - (qrc - uc);
        int rB  = min(max((int)qlc - 2, 0), 127);
        int rBr = min(max((int)qrc - 2, 0), 127);
        off[8]=rB*Wdim+cm[1]; off[9]=rB*Wdim+cm[2]; off[10]=rB*Wdim+cm[3]; off[11]=rB*Wdim+cm[4];
        eBw  = (w == 127) ? aBr : 0.f;
        eBoff = rBr*Wdim + 127;
        u = (float)w - gb[2];
        q = floorf(u);
        qlc = fminf(fmaxf(q, 0.f), 131.f);
        qrc = fminf(fmaxf(q + 1.f, 0.f), 131.f);
        uc  = fminf(fmaxf(u, 0.f), 131.f);
        a[3] = 1.f + qlc - uc;
        float aLr = 1.f - (qrc - uc);
        int cL  = min(max((int)qlc - 2, 0), 127);
        int cLr = min(max((int)qrc - 2, 0), 127);
        off[12]=rm[1]*Wdim+cL; off[13]=rm[2]*Wdim+cL; off[14]=rm[3]*Wdim+cL; off[15]=rm[4]*Wdim+cL;
        eLw  = (h == 127) ? aLr : 0.f;
        eLoff = 127*Wdim + cLr;

        #pragma unroll
        for (int j = 0; j < 8; ++j)
            offp[j] = (unsigned int)off[2*j] | ((unsigned int)off[2*j+1] << 16);
    }

    const float* Xb = x + (size_t)b*Cdim*HW;
    int ctr = h*Wdim + w;

    // fragment addresses
    uint32_t sb32 = smem_u32(smem);
    uint32_t aRow = (uint32_t)(wid*16 + (lid & 15));
    uint32_t aCol = (uint32_t)((lid >> 4) * 16);
    uint32_t aAddr0 = sb32 + SM_A + aRow*80 + aCol;       // A parity 0
    uint32_t bRow = (uint32_t)(lid & 7);
    uint32_t bCol = (uint32_t)(((lid >> 3) & 1) * 16);
    uint32_t bAddr = sb32 + SM_B + bRow*1040 + bCol;

    float acc[4][4];
    #pragma unroll
    for (int nt = 0; nt < 4; ++nt)
        #pragma unroll
        for (int r = 0; r < 4; ++r) acc[nt][r] = 0.f;

    float pf[19];
    // chunk 0: channel chp
    ldch(Xb + chp*HW, ctr, offp, eBoff, eLoff, eBw, eLw, pf);
    __syncthreads();                       // B plane + bias ready
    cvtstore(smem, pf, a, eBw, eLw, p, chp, 0);
    __syncthreads();                       // chunk 0 ready

    #pragma unroll 1
    for (int cc = 1; cc < 16; ++cc) {
        // issue gathers for chunk cc (latency hidden under mma below)
        ldch(Xb + (2*cc + chp)*HW, ctr, offp, eBoff, eLoff, eBw, eLw, pf);

        // consume chunk cc-1 from parity (cc-1)&1
        {
            int pcons = (cc - 1) & 1;
            uint32_t aH = aAddr0 + (uint32_t)(pcons*APLANE);
            uint32_t bOff = (uint32_t)((cc - 1)*64);
            #pragma unroll
            for (int kt = 0; kt < 2; ++kt) {
                uint32_t ah[4];
                ldmx4(ah, aH + kt*32);
                #pragma unroll
                for (int nt = 0; nt < 4; ++nt) {
                    uint32_t bf[2];
                    ldmx2(bf, bAddr + nt*8320 + bOff + kt*32);
                    mma_f16(acc[nt], ah, bf);
                }
            }
        }

        // store chunk cc into parity cc&1
        cvtstore(smem, pf, a, eBw, eLw, p, chp, cc & 1);
        __syncthreads();
    }

    // final chunk 15 (parity 1)
    {
        uint32_t aH = aAddr0 + (uint32_t)APLANE;
        uint32_t bOff = (uint32_t)(15*64);
        #pragma unroll
        for (int kt = 0; kt < 2; ++kt) {
            uint32_t ah[4];
            ldmx4(ah, aH + kt*32);
            #pragma unroll
            for (int nt = 0; nt < 4; ++nt) {
                uint32_t bf[2];
                ldmx2(bf, bAddr + nt*8320 + bOff + kt*32);
                mma_f16(acc[nt], ah, bf);
            }
        }
    }

    // epilogue
    int g = lid >> 2, tig = lid & 3;
    int p0 = wid*16 + g;
    #pragma unroll
    for (int nt = 0; nt < 4; ++nt) {
        int o0 = nt*8 + 2*tig;
        float b0f = sbias[o0], b1f = sbias[o0+1];
        size_t obase = ((size_t)b*OUTdim + o0)*HW + (size_t)row*Wdim;
        out[obase +      p0    ] = acc[nt][0] + b0f;
        out[obase + HW + p0    ] = acc[nt][1] + b1f;
        out[obase +      p0 + 8] = acc[nt][2] + b0f;
        out[obase + HW + p0 + 8] = acc[nt][3] + b1f;
    }
}

// =====================================================================
extern "C" void kernel_launch(void* const* d_in, const int* in_sizes, int n_in,
                              void* d_out, int out_size)
{
    const float* x      = (const float*)d_in[0];
    const float* w_vrt  = (const float*)d_in[1];
    const float* b_vrt  = (const float*)d_in[2];
    const float* g_vrt  = (const float*)d_in[3];
    const float* be_vrt = (const float*)d_in[4];
    const float* w_hrz  = (const float*)d_in[5];
    const float* b_hrz  = (const float*)d_in[6];
    const float* g_hrz  = (const float*)d_in[7];
    const float* be_hrz = (const float*)d_in[8];
    const float* w_pk   = (const float*)d_in[9];
    const float* b_pk   = (const float*)d_in[10];
    float* out = (float*)d_out;

    convbn_kernel<<<NBLK_CONV, 256>>>(x, w_vrt, b_vrt, w_hrz, b_hrz, w_pk);
    stats_kernel<<<1, 256>>>(g_vrt, be_vrt, g_hrz, be_hrz);

    cudaFuncSetAttribute(main_kernel, cudaFuncAttributeMaxDynamicSharedMemorySize, SM_TOTAL);
    main_kernel<<<NPIX/128, 256, SM_TOTAL>>>(x, b_pk, out);
}

// round 17
// speedup vs baseline: 1.2291x; 1.2291x over previous
#include <cuda_runtime.h>
#include <cuda_fp16.h>
#include <math.h>
#include <stdint.h>

#define Bdim 8
#define Cdim 32
#define Hdim 128
#define Wdim 128
#define OUTdim 32
#define HW (Hdim*Wdim)            /* 16384 */
#define NPIX (Bdim*HW)            /* 131072 */
#define NBLK_CONV 512

// ---- scratch (static device globals; no runtime allocation) ----
__device__ float g_conv[4*NPIX];          // conv+bias outputs: v0,v1,z0,z1 planes
__device__ float g_partial[NBLK_CONV*8];  // per-block partial sums (4 sums + 4 sumsq)
__device__ float g_stats[12];             // mean[4], scale[4], shift[4]
__device__ __align__(16) __half g_bh[32*512];  // w_pk fp16 plane

// =====================================================================
// Kernel A (fused): 7-tap convs + bias + BN block partials + w_pk->fp16
// =====================================================================
__global__ __launch_bounds__(256) void convbn_kernel(
    const float* __restrict__ x,
    const float* __restrict__ w_vrt, const float* __restrict__ b_vrt,
    const float* __restrict__ w_hrz, const float* __restrict__ b_hrz,
    const float* __restrict__ w_pk)
{
    __shared__ float swv[448], swh[448];
    __shared__ float part[4][256];       // [plane][rowsel*128 + w]
    __shared__ float red[4][8];
    int tid = threadIdx.x;
    for (int i = tid; i < 448; i += 256) { swv[i] = w_vrt[i]; swh[i] = w_hrz[i]; }
    // fused wsplit: each block converts its 32-element slice of w_pk
    if (tid < 32) {
        int i = blockIdx.x*32 + tid;
        g_bh[i] = __float2half_rn(w_pk[i]);
    }
    __syncthreads();

    int b      = blockIdx.x >> 6;
    int rg     = blockIdx.x & 63;
    int rowsel = (tid >> 6) & 1;
    int half   = tid >> 7;
    int row    = rg*2 + rowsel;
    int w0     = (tid & 63) * 2;
    const float* Xb = x + (size_t)b*Cdim*HW;

    float v0[2]={0,0}, v1[2]={0,0}, z0[2]={0,0}, z1[2]={0,0};

    #pragma unroll 1
    for (int cl = 0; cl < 16; ++cl) {
        int c = half*16 + cl;
        const float* Xc  = Xb + c*HW;
        const float* rp  = Xc + row*Wdim;
        #pragma unroll
        for (int t = 0; t < 7; ++t) {
            int hh = row + t - 3;
            float2 xv = (hh >= 0 && hh < Hdim) ? *(const float2*)(Xc + hh*Wdim + w0)
                                               : make_float2(0.f, 0.f);
            float wa = swv[c*7+t], wb = swv[224 + c*7+t];
            v0[0]=fmaf(xv.x,wa,v0[0]); v0[1]=fmaf(xv.y,wa,v0[1]);
            v1[0]=fmaf(xv.x,wb,v1[0]); v1[1]=fmaf(xv.y,wb,v1[1]);
        }
        float xr[10];
        #pragma unroll
        for (int l = 0; l < 5; ++l) {
            int i0 = w0 - 4 + l*2;
            float2 v = (i0 >= 0 && i0 < 127) ? *(const float2*)(rp + i0)
                                             : make_float2(0.f, 0.f);
            xr[l*2] = v.x; xr[l*2+1] = v.y;
        }
        #pragma unroll
        for (int t = 0; t < 7; ++t) {
            float wa = swh[c*7+t], wb = swh[224 + c*7+t];
            z0[0]=fmaf(xr[t+1],wa,z0[0]); z0[1]=fmaf(xr[t+2],wa,z0[1]);
            z1[0]=fmaf(xr[t+1],wb,z1[0]); z1[1]=fmaf(xr[t+2],wb,z1[1]);
        }
    }

    int sp = rowsel*128 + w0;
    if (half == 1) {
        *(float2*)&part[0][sp] = make_float2(v0[0], v0[1]);
        *(float2*)&part[1][sp] = make_float2(v1[0], v1[1]);
        *(float2*)&part[2][sp] = make_float2(z0[0], z0[1]);
        *(float2*)&part[3][sp] = make_float2(z1[0], z1[1]);
    }
    __syncthreads();

    if (half == 0) {
        float2 o0 = *(float2*)&part[0][sp];
        float2 o1 = *(float2*)&part[1][sp];
        float2 o2 = *(float2*)&part[2][sp];
        float2 o3 = *(float2*)&part[3][sp];
        float bv0 = b_vrt[0], bv1 = b_vrt[1], bh0 = b_hrz[0], bh1 = b_hrz[1];
        v0[0] += o0.x + bv0; v0[1] += o0.y + bv0;
        v1[0] += o1.x + bv1; v1[1] += o1.y + bv1;
        z0[0] += o2.x + bh0; z0[1] += o2.y + bh0;
        z1[0] += o3.x + bh1; z1[1] += o3.y + bh1;

        int pixbase = b*HW + row*Wdim + w0;
        *(float2*)&g_conv[          pixbase] = make_float2(v0[0],v0[1]);
        *(float2*)&g_conv[  NPIX +  pixbase] = make_float2(v1[0],v1[1]);
        *(float2*)&g_conv[2*NPIX +  pixbase] = make_float2(z0[0],z0[1]);
        *(float2*)&g_conv[3*NPIX +  pixbase] = make_float2(z1[0],z1[1]);

        float vals[8];
        vals[0]=v0[0]+v0[1]; vals[1]=v1[0]+v1[1]; vals[2]=z0[0]+z0[1]; vals[3]=z1[0]+z1[1];
        vals[4]=v0[0]*v0[0]+v0[1]*v0[1]; vals[5]=v1[0]*v1[0]+v1[1]*v1[1];
        vals[6]=z0[0]*z0[0]+z0[1]*z0[1]; vals[7]=z1[0]*z1[0]+z1[1]*z1[1];

        #pragma unroll
        for (int k = 0; k < 8; ++k) {
            float s = vals[k];
            #pragma unroll
            for (int off = 16; off; off >>= 1) s += __shfl_down_sync(0xffffffffu, s, off);
            if ((tid & 31) == 0) red[tid>>5][k] = s;
        }
    }
    __syncthreads();
    if (tid < 8) {
        float s = red[0][tid] + red[1][tid] + red[2][tid] + red[3][tid];
        g_partial[blockIdx.x*8 + tid] = s;
    }
}

// =====================================================================
// Kernel B: finalize BN stats — parallel reduction
// =====================================================================
__global__ __launch_bounds__(256) void stats_kernel(
    const float* __restrict__ g_vrt, const float* __restrict__ be_vrt,
    const float* __restrict__ g_hrz, const float* __restrict__ be_hrz)
{
    __shared__ float red[32][8];
    __shared__ float sh[8];
    int t = threadIdx.x;
    int k = t & 7, grp = t >> 3;

    float s = 0.f;
    #pragma unroll
    for (int j = 0; j < 16; ++j)
        s += g_partial[(grp + 32*j)*8 + k];
    red[grp][k] = s;
    __syncthreads();

    if (t < 8) {
        float acc = 0.f;
        #pragma unroll
        for (int g = 0; g < 32; ++g) acc += red[g][t];
        sh[t] = acc;
    }
    __syncthreads();

    if (t < 4) {
        const float inv = 1.f / (float)NPIX;
        float mean = sh[t] * inv;
        float var  = sh[t+4] * inv - mean*mean;
        float gamma = (t < 2) ? g_vrt[t] : g_hrz[t-2];
        float beta  = (t < 2) ? be_vrt[t] : be_hrz[t-2];
        g_stats[t]     = mean;
        g_stats[4 + t] = gamma * rsqrtf(var + 1e-5f);
        g_stats[8 + t] = beta;
    }
}

// =====================================================================
// Kernel C: fp16 1-GEMM, symmetric ping-pong, 3 CTAs/SM (known-good).
// =====================================================================
#define BSTRIDE 520    /* halfs per B row -> 1040 B */
#define APLANE  10240  /* 128 rows x 80 B */

#define SM_BIAS 0
#define SM_B    128
#define SM_A    (SM_B + 32*BSTRIDE*2)           /* 33408; A0, A1 (parities) */
#define SM_TOTAL (SM_A + 2*APLANE)              /* 53888 */

__device__ __forceinline__ uint32_t smem_u32(const void* p) {
    uint32_t a;
    asm("{ .reg .u64 t; cvta.to.shared.u64 t, %1; cvt.u32.u64 %0, t; }" : "=r"(a) : "l"(p));
    return a;
}
__device__ __forceinline__ void mma_f16(float* c, const uint32_t* a, const uint32_t* b) {
    asm volatile(
        "mma.sync.aligned.m16n8k16.row.col.f32.f16.f16.f32 "
        "{%0,%1,%2,%3}, {%4,%5,%6,%7}, {%8,%9}, {%0,%1,%2,%3};"
        : "+f"(c[0]), "+f"(c[1]), "+f"(c[2]), "+f"(c[3])
        : "r"(a[0]), "r"(a[1]), "r"(a[2]), "r"(a[3]), "r"(b[0]), "r"(b[1]));
}
__device__ __forceinline__ void ldmx4(uint32_t* r, uint32_t addr) {
    asm volatile("ldmatrix.sync.aligned.m8n8.x4.shared.b16 {%0,%1,%2,%3}, [%4];"
        : "=r"(r[0]), "=r"(r[1]), "=r"(r[2]), "=r"(r[3]) : "r"(addr));
}
__device__ __forceinline__ void ldmx2(uint32_t* r, uint32_t addr) {
    asm volatile("ldmatrix.sync.aligned.m8n8.x2.shared.b16 {%0,%1}, [%2];"
        : "=r"(r[0]), "=r"(r[1]) : "r"(addr));
}

// raw gather of one channel: xc, 16 ring samples, 2 predicated edge samples
__device__ __forceinline__ void ldch(const float* __restrict__ Xc, int ctr,
                                     const unsigned* offp, int eBoff, int eLoff,
                                     float eBw, float eLw, float* r) {
    r[0] = __ldg(Xc + ctr);
    #pragma unroll
    for (int j = 0; j < 8; ++j) {
        r[1+2*j] = __ldg(Xc + (int)(offp[j] & 0xFFFFu));
        r[2+2*j] = __ldg(Xc + (int)(offp[j] >> 16));
    }
    r[17] = (eBw != 0.f) ? __ldg(Xc + eBoff) : 0.f;
    r[18] = (eLw != 0.f) ? __ldg(Xc + eLoff) : 0.f;
}

// convert one channel's 16 taps (single fp16), store into A plane [par]
__device__ __forceinline__ void cvtstore(char* smem, const float* r, const float* a,
                                         float eBw, float eLw, int p, int chp, int par) {
    float d[16];
    #pragma unroll
    for (int n = 0; n < 16; ++n)
        d[n] = fmaf(-a[n>>2], r[1+n], r[0]);
    d[11] = fmaf(-eBw, r[17], d[11]);
    d[15] = fmaf(-eLw, r[18], d[15]);

    uint32_t oh[8];
    #pragma unroll
    for (int j = 0; j < 8; ++j) {
        __half2 hv = __float22half2_rn(make_float2(d[2*j], d[2*j+1]));
        oh[j] = *(uint32_t*)&hv;
    }
    char* baseH = smem + SM_A + par*APLANE + p*80 + chp*32;
    ((uint4*)baseH)[0] = make_uint4(oh[0], oh[1], oh[2], oh[3]);
    ((uint4*)baseH)[1] = make_uint4(oh[4], oh[5], oh[6], oh[7]);
}

__global__ __launch_bounds__(256, 3) void main_kernel(
    const float* __restrict__ x, const float* __restrict__ b_pk,
    float* __restrict__ out)
{
    extern __shared__ char smem[];
    float* sbias = (float*)(smem + SM_BIAS);
    int tid = threadIdx.x;
    int wid = tid >> 5, lid = tid & 31;

    // --- copy fp16 B plane into padded smem rows ---
    {
        if (tid < 32) sbias[tid] = b_pk[tid];
        const uint4* sbh = (const uint4*)g_bh;
        #pragma unroll
        for (int j = 0; j < 8; ++j) {
            int u = tid + j*256;
            int o = u >> 6, q = u & 63;
            *(uint4*)(smem + SM_B + o*(BSTRIDE*2) + q*16) = sbh[u];
        }
    }

    int b   = blockIdx.x >> 7;
    int row = blockIdx.x & 127;
    int p   = tid & 127;
    int chp = tid >> 7;              // channel-in-chunk selector (0/1)
    int h = row, w = p;
    int pix = b*HW + row*Wdim + w;

    // gb0..gb3 = 2*sigmoid(BN(conv))
    float gb[4];
    #pragma unroll
    for (int j = 0; j < 4; ++j) {
        float cv = g_conv[j*NPIX + pix];
        float t = (cv - g_stats[j]) * g_stats[4+j] + g_stats[8+j];
        gb[j] = 2.f / (1.f + expf(-t));
    }

    int rm[5], cm[5];
    #pragma unroll
    for (int i = 0; i < 5; ++i) {
        rm[i] = min(max(h + i - 2, 0), 127);
        cm[i] = min(max(w + i - 2, 0), 127);
    }

    unsigned int offp[8];
    float a[4];
    float eBw, eLw; int eBoff, eLoff;
    {
        int off[16];
        float u, q, qlc, qrc, uc;
        u = (float)h - gb[0];
        q = floorf(u);
        qlc = fminf(fmaxf(q, 0.f), 131.f);
        uc  = fminf(fmaxf(u, 0.f), 131.f);
        a[0] = 1.f + qlc - uc;
        int rT = min(max((int)qlc - 2, 0), 127);
        off[0]=rT*Wdim+cm[0]; off[1]=rT*Wdim+cm[1]; off[2]=rT*Wdim+cm[2]; off[3]=rT*Wdim+cm[3];
        u = (float)w + 4.f + gb[3];
        q = floorf(u);
        qlc = fminf(fmaxf(q, 0.f), 131.f);
        uc  = fminf(fmaxf(u, 0.f), 131.f);
        a[1] = 1.f + qlc - uc;
        int cR = min(max((int)qlc - 2, 0), 127);
        off[4]=rm[0]*Wdim+cR; off[5]=rm[1]*Wdim+cR; off[6]=rm[2]*Wdim+cR; off[7]=rm[3]*Wdim+cR;
        u = (float)h + 4.f + gb[1];
        q = floorf(u);
        qlc = fminf(fmaxf(q, 0.f), 131.f);
        qrc = fminf(fmaxf(q + 1.f, 0.f), 131.f);
        uc  = fminf(fmaxf(u, 0.f), 131.f);
        a[2] = 1.f + qlc - uc;
        float aBr = 1.f - (qrc - uc);
        int rB  = min(max((int)qlc - 2, 0), 127);
        int rBr = min(max((int)qrc - 2, 0), 127);
        off[8]=rB*Wdim+cm[1]; off[9]=rB*Wdim+cm[2]; off[10]=rB*Wdim+cm[3]; off[11]=rB*Wdim+cm[4];
        eBw  = (w == 127) ? aBr : 0.f;
        eBoff = rBr*Wdim + 127;
        u = (float)w - gb[2];
        q = floorf(u);
        qlc = fminf(fmaxf(q, 0.f), 131.f);
        qrc = fminf(fmaxf(q + 1.f, 0.f), 131.f);
        uc  = fminf(fmaxf(u, 0.f), 131.f);
        a[3] = 1.f + qlc - uc;
        float aLr = 1.f - (qrc - uc);
        int cL  = min(max((int)qlc - 2, 0), 127);
        int cLr = min(max((int)qrc - 2, 0), 127);
        off[12]=rm[1]*Wdim+cL; off[13]=rm[2]*Wdim+cL; off[14]=rm[3]*Wdim+cL; off[15]=rm[4]*Wdim+cL;
        eLw  = (h == 127) ? aLr : 0.f;
        eLoff = 127*Wdim + cLr;

        #pragma unroll
        for (int j = 0; j < 8; ++j)
            offp[j] = (unsigned int)off[2*j] | ((unsigned int)off[2*j+1] << 16);
    }

    const float* Xb = x + (size_t)b*Cdim*HW;
    int ctr = h*Wdim + w;

    // fragment addresses
    uint32_t sb32 = smem_u32(smem);
    uint32_t aRow = (uint32_t)(wid*16 + (lid & 15));
    uint32_t aCol = (uint32_t)((lid >> 4) * 16);
    uint32_t aAddr0 = sb32 + SM_A + aRow*80 + aCol;       // A parity 0
    uint32_t bRow = (uint32_t)(lid & 7);
    uint32_t bCol = (uint32_t)(((lid >> 3) & 1) * 16);
    uint32_t bAddr = sb32 + SM_B + bRow*1040 + bCol;

    float acc[4][4];
    #pragma unroll
    for (int nt = 0; nt < 4; ++nt)
        #pragma unroll
        for (int r = 0; r < 4; ++r) acc[nt][r] = 0.f;

    float pf[19];
    // chunk 0: channel chp
    ldch(Xb + chp*HW, ctr, offp, eBoff, eLoff, eBw, eLw, pf);
    __syncthreads();                       // B plane + bias ready
    cvtstore(smem, pf, a, eBw, eLw, p, chp, 0);
    __syncthreads();                       // chunk 0 ready

    #pragma unroll 1
    for (int cc = 1; cc < 16; ++cc) {
        // issue gathers for chunk cc (latency hidden under mma below)
        ldch(Xb + (2*cc + chp)*HW, ctr, offp, eBoff, eLoff, eBw, eLw, pf);

        // consume chunk cc-1 from parity (cc-1)&1
        {
            int pcons = (cc - 1) & 1;
            uint32_t aH = aAddr0 + (uint32_t)(pcons*APLANE);
            uint32_t bOff = (uint32_t)((cc - 1)*64);
            #pragma unroll
            for (int kt = 0; kt < 2; ++kt) {
                uint32_t ah[4];
                ldmx4(ah, aH + kt*32);
                #pragma unroll
                for (int nt = 0; nt < 4; ++nt) {
                    uint32_t bf[2];
                    ldmx2(bf, bAddr + nt*8320 + bOff + kt*32);
                    mma_f16(acc[nt], ah, bf);
                }
            }
        }

        // store chunk cc into parity cc&1
        cvtstore(smem, pf, a, eBw, eLw, p, chp, cc & 1);
        __syncthreads();
    }

    // final chunk 15 (parity 1)
    {
        uint32_t aH = aAddr0 + (uint32_t)APLANE;
        uint32_t bOff = (uint32_t)(15*64);
        #pragma unroll
        for (int kt = 0; kt < 2; ++kt) {
            uint32_t ah[4];
            ldmx4(ah, aH + kt*32);
            #pragma unroll
            for (int nt = 0; nt < 4; ++nt) {
                uint32_t bf[2];
                ldmx2(bf, bAddr + nt*8320 + bOff + kt*32);
                mma_f16(acc[nt], ah, bf);
            }
        }
    }

    // epilogue
    int g = lid >> 2, tig = lid & 3;
    int p0 = wid*16 + g;
    #pragma unroll
    for (int nt = 0; nt < 4; ++nt) {
        int o0 = nt*8 + 2*tig;
        float b0f = sbias[o0], b1f = sbias[o0+1];
        size_t obase = ((size_t)b*OUTdim + o0)*HW + (size_t)row*Wdim;
        out[obase +      p0    ] = acc[nt][0] + b0f;
        out[obase + HW + p0    ] = acc[nt][1] + b1f;
        out[obase +      p0 + 8] = acc[nt][2] + b0f;
        out[obase + HW + p0 + 8] = acc[nt][3] + b1f;
    }
}

// =====================================================================
extern "C" void kernel_launch(void* const* d_in, const int* in_sizes, int n_in,
                              void* d_out, int out_size)
{
    const float* x      = (const float*)d_in[0];
    const float* w_vrt  = (const float*)d_in[1];
    const float* b_vrt  = (const float*)d_in[2];
    const float* g_vrt  = (const float*)d_in[3];
    const float* be_vrt = (const float*)d_in[4];
    const float* w_hrz  = (const float*)d_in[5];
    const float* b_hrz  = (const float*)d_in[6];
    const float* g_hrz  = (const float*)d_in[7];
    const float* be_hrz = (const float*)d_in[8];
    const float* w_pk   = (const float*)d_in[9];
    const float* b_pk   = (const float*)d_in[10];
    float* out = (float*)d_out;

    convbn_kernel<<<NBLK_CONV, 256>>>(x, w_vrt, b_vrt, w_hrz, b_hrz, w_pk);
    stats_kernel<<<1, 256>>>(g_vrt, be_vrt, g_hrz, be_hrz);

    cudaFuncSetAttribute(main_kernel, cudaFuncAttributeMaxDynamicSharedMemorySize, SM_TOTAL);
    main_kernel<<<NPIX/128, 256, SM_TOTAL>>>(x, b_pk, out);
}